// round 1
// baseline (speedup 1.0000x reference)
#include <cuda_runtime.h>
#include <cuda_bf16.h>
#include <cstdint>

// Problem constants
#define EMBED 1024
#define NHEAD 16
#define HDIM  64
#define TLEN  1024
#define BSZ   4
#define MROWS (TLEN*BSZ)          // 4096
#define SCALE 0.03125f            // 1/sqrt(1024)

// ---------------------------------------------------------------------------
// Scratch (no allocations allowed -> device globals)
// ---------------------------------------------------------------------------
__device__ float g_q[(size_t)MROWS * EMBED];
__device__ float g_k[(size_t)MROWS * EMBED];
__device__ float g_v[(size_t)MROWS * EMBED];
__device__ float g_o[(size_t)MROWS * EMBED];

// ---------------------------------------------------------------------------
// NT GEMM:  C[m,n] = sum_k X[m,k] * W[n,k] + bias[n]
// X: [M,K] row-major, W: [N,K] row-major. M=4096, N=1024, K=1024 here.
// 128x128 block tile, BK=16, 256 threads, 8x8 per-thread register tile.
// ---------------------------------------------------------------------------
#define GBM 128
#define GBN 128
#define GBK 16

__global__ void __launch_bounds__(256, 2) gemm_nt_kernel(
    const float* __restrict__ X, const float* __restrict__ W,
    const float* __restrict__ bias, float* __restrict__ C,
    int M, int N, int K)
{
    __shared__ float As[GBK][GBM];
    __shared__ float Bs[GBK][GBN];

    const int tid = threadIdx.x;
    const int tx  = tid & 15;      // 0..15 -> n
    const int ty  = tid >> 4;      // 0..15 -> m
    const int m0  = blockIdx.y * GBM;
    const int n0  = blockIdx.x * GBN;

    float acc[8][8];
#pragma unroll
    for (int i = 0; i < 8; i++)
#pragma unroll
        for (int j = 0; j < 8; j++) acc[i][j] = 0.f;

    for (int k0 = 0; k0 < K; k0 += GBK) {
        // Load 128x16 tiles of X and W, stored k-major in smem.
#pragma unroll
        for (int it = 0; it < 2; it++) {
            int idx = tid + it * 256;       // 0..511
            int row = idx >> 2;             // 0..127
            int c4  = (idx & 3) << 2;       // 0,4,8,12
            float4 xv = *(const float4*)&X[(size_t)(m0 + row) * K + k0 + c4];
            As[c4 + 0][row] = xv.x; As[c4 + 1][row] = xv.y;
            As[c4 + 2][row] = xv.z; As[c4 + 3][row] = xv.w;
            float4 wv = *(const float4*)&W[(size_t)(n0 + row) * K + k0 + c4];
            Bs[c4 + 0][row] = wv.x; Bs[c4 + 1][row] = wv.y;
            Bs[c4 + 2][row] = wv.z; Bs[c4 + 3][row] = wv.w;
        }
        __syncthreads();

#pragma unroll
        for (int k = 0; k < GBK; k++) {
            float4 a0 = *(const float4*)&As[k][ty * 8];
            float4 a1 = *(const float4*)&As[k][ty * 8 + 4];
            float4 b0 = *(const float4*)&Bs[k][tx * 8];
            float4 b1 = *(const float4*)&Bs[k][tx * 8 + 4];
            float a[8] = {a0.x, a0.y, a0.z, a0.w, a1.x, a1.y, a1.z, a1.w};
            float b[8] = {b0.x, b0.y, b0.z, b0.w, b1.x, b1.y, b1.z, b1.w};
#pragma unroll
            for (int i = 0; i < 8; i++)
#pragma unroll
                for (int j = 0; j < 8; j++) acc[i][j] = fmaf(a[i], b[j], acc[i][j]);
        }
        __syncthreads();
    }

    // Epilogue + bias
#pragma unroll
    for (int i = 0; i < 8; i++) {
        size_t crow = (size_t)(m0 + ty * 8 + i) * N + n0 + tx * 8;
#pragma unroll
        for (int j4 = 0; j4 < 2; j4++) {
            int nb = n0 + tx * 8 + j4 * 4;
            float4 o;
            o.x = acc[i][j4 * 4 + 0] + bias[nb + 0];
            o.y = acc[i][j4 * 4 + 1] + bias[nb + 1];
            o.z = acc[i][j4 * 4 + 2] + bias[nb + 2];
            o.w = acc[i][j4 * 4 + 3] + bias[nb + 3];
            *(float4*)&C[crow + j4 * 4] = o;
        }
    }
}

// ---------------------------------------------------------------------------
// Fused sigmoid-attention kernel.
// grid = (16 t-tiles, 64 bh). block = 256 threads (16x16, 4x4 per thread).
// Per block: Q tile [64,64] resident; stream K/V tiles of 64 rows.
//   S = sigmoid(Q K^T * SCALE)  -> written to attn output (coalesced)
//   O += S * V                  -> register accumulators
// Dynamic smem: Qs[64][68] (d-major), Ks[64][68] (d-major),
//               Ss[64][68] (i-major), Vs[64][68] (j-major)  = 69632 B
// ---------------------------------------------------------------------------
#define APAD 68
#define ATTN_SMEM (4 * 64 * APAD * 4)

__global__ void __launch_bounds__(256, 1) attn_kernel(
    const float* __restrict__ q, const float* __restrict__ k,
    const float* __restrict__ v, float* __restrict__ o,
    float* __restrict__ attn)
{
    extern __shared__ float sm[];
    float* Qs = sm;                    // [d][i]
    float* Ks = Qs + 64 * APAD;        // [d][j]
    float* Ss = Ks + 64 * APAD;        // [i][j]
    float* Vs = Ss + 64 * APAD;        // [j][d]

    const int tid = threadIdx.x;
    const int tx  = tid & 15;
    const int ty  = tid >> 4;
    const int t0  = blockIdx.x * 64;
    const int bh  = blockIdx.y;
    const int b   = bh / NHEAD;
    const int h   = bh % NHEAD;
    const size_t head_off = (size_t)h * HDIM;

    // Load Q tile (scaled), store d-major
    for (int idx = tid; idx < 64 * 64; idx += 256) {
        int i = idx >> 6, d = idx & 63;
        Qs[d * APAD + i] = q[((size_t)(t0 + i) * BSZ + b) * EMBED + head_off + d] * SCALE;
    }

    float acc_o[4][4];
#pragma unroll
    for (int i = 0; i < 4; i++)
#pragma unroll
        for (int j = 0; j < 4; j++) acc_o[i][j] = 0.f;

    for (int s0 = 0; s0 < TLEN; s0 += 64) {
        __syncthreads();   // Qs ready (iter 0) / previous iter done with Ks/Vs/Ss
        // Load K (d-major) and V (j-major) tiles
        for (int idx = tid; idx < 64 * 64; idx += 256) {
            int j = idx >> 6, d = idx & 63;
            size_t gro = ((size_t)(s0 + j) * BSZ + b) * EMBED + head_off + d;
            Ks[d * APAD + j] = k[gro];
            Vs[j * APAD + d] = v[gro];
        }
        __syncthreads();

        // S = sigmoid(Q K^T)
        float accs[4][4];
#pragma unroll
        for (int i = 0; i < 4; i++)
#pragma unroll
            for (int j = 0; j < 4; j++) accs[i][j] = 0.f;

#pragma unroll 8
        for (int d = 0; d < 64; d++) {
            float4 aq = *(const float4*)&Qs[d * APAD + ty * 4];
            float4 bk = *(const float4*)&Ks[d * APAD + tx * 4];
            float a[4] = {aq.x, aq.y, aq.z, aq.w};
            float bb[4] = {bk.x, bk.y, bk.z, bk.w};
#pragma unroll
            for (int i = 0; i < 4; i++)
#pragma unroll
                for (int j = 0; j < 4; j++) accs[i][j] = fmaf(a[i], bb[j], accs[i][j]);
        }
#pragma unroll
        for (int i = 0; i < 4; i++)
#pragma unroll
            for (int j = 0; j < 4; j++) {
                float s = 1.0f / (1.0f + __expf(-accs[i][j]));
                Ss[(ty * 4 + i) * APAD + tx * 4 + j] = s;
            }
        __syncthreads();

        // Write S tile to gmem attn output (coalesced rows of 64 floats)
        {
            size_t base = ((size_t)bh * TLEN + t0) * TLEN + s0;
            for (int idx = tid; idx < 64 * 64; idx += 256) {
                int i = idx >> 6, j = idx & 63;
                attn[base + (size_t)i * TLEN + j] = Ss[i * APAD + j];
            }
        }

        // O += S * V
#pragma unroll 8
        for (int j = 0; j < 64; j++) {
            float4 bv = *(const float4*)&Vs[j * APAD + tx * 4];
            float bb[4] = {bv.x, bv.y, bv.z, bv.w};
#pragma unroll
            for (int i = 0; i < 4; i++) {
                float a = Ss[(ty * 4 + i) * APAD + j];
#pragma unroll
                for (int d = 0; d < 4; d++) acc_o[i][d] = fmaf(a, bb[d], acc_o[i][d]);
            }
        }
    }

    // Write O tile
#pragma unroll
    for (int i = 0; i < 4; i++) {
        int t = t0 + ty * 4 + i;
        float4 ov = {acc_o[i][0], acc_o[i][1], acc_o[i][2], acc_o[i][3]};
        *(float4*)&o[((size_t)t * BSZ + b) * EMBED + head_off + tx * 4] = ov;
    }
}

// ---------------------------------------------------------------------------
// Launch
// ---------------------------------------------------------------------------
extern "C" void kernel_launch(void* const* d_in, const int* in_sizes, int n_in,
                              void* d_out, int out_size)
{
    const float* query = (const float*)d_in[0];
    const float* keyt  = (const float*)d_in[1];
    const float* value = (const float*)d_in[2];
    const float* w_in  = (const float*)d_in[3];   // [3E, E]
    const float* b_in  = (const float*)d_in[4];   // [3E]
    const float* w_out = (const float*)d_in[5];   // [E, E]
    const float* b_out = (const float*)d_in[6];   // [E]

    float* out  = (float*)d_out;                               // attn_output [T,B,E]
    float* attn = out + (size_t)TLEN * BSZ * EMBED;            // attn [B*H,T,T]

    float *q, *k, *v, *o;
    cudaGetSymbolAddress((void**)&q, g_q);
    cudaGetSymbolAddress((void**)&k, g_k);
    cudaGetSymbolAddress((void**)&v, g_v);
    cudaGetSymbolAddress((void**)&o, g_o);

    dim3 gblk(256);
    dim3 ggrid(EMBED / GBN, MROWS / GBM);

    // QKV projections
    gemm_nt_kernel<<<ggrid, gblk>>>(query, w_in,                           b_in,             q, MROWS, EMBED, EMBED);
    gemm_nt_kernel<<<ggrid, gblk>>>(keyt,  w_in + (size_t)EMBED * EMBED,   b_in + EMBED,     k, MROWS, EMBED, EMBED);
    gemm_nt_kernel<<<ggrid, gblk>>>(value, w_in + (size_t)2 * EMBED * EMBED, b_in + 2 * EMBED, v, MROWS, EMBED, EMBED);

    // Fused attention
    cudaFuncSetAttribute(attn_kernel, cudaFuncAttributeMaxDynamicSharedMemorySize, ATTN_SMEM);
    attn_kernel<<<dim3(TLEN / 64, BSZ * NHEAD), 256, ATTN_SMEM>>>(q, k, v, o, attn);

    // Output projection
    gemm_nt_kernel<<<ggrid, gblk>>>(o, w_out, b_out, out, MROWS, EMBED, EMBED);
}

// round 2
// speedup vs baseline: 2.0751x; 2.0751x over previous
#include <cuda_runtime.h>
#include <cuda_bf16.h>
#include <cstdint>

#define EMBED 1024
#define NHEAD 16
#define HDIM  64
#define TLEN  1024
#define BSZ   4
#define MROWS (TLEN*BSZ)          // 4096
#define SCALE 0.03125f            // 1/sqrt(1024)

// Scratch
__device__ float g_q[(size_t)MROWS * EMBED];
__device__ float g_k[(size_t)MROWS * EMBED];
__device__ float g_v[(size_t)MROWS * EMBED];
__device__ float g_o[(size_t)MROWS * EMBED];

// ---------------------------------------------------------------------------
// tf32 helpers
// ---------------------------------------------------------------------------
__device__ __forceinline__ uint32_t f2tf(float x) {
    uint32_t r;
    asm("cvt.rna.tf32.f32 %0, %1;" : "=r"(r) : "f"(x));
    return r;
}
__device__ __forceinline__ float tf32r(float x) { return __uint_as_float(f2tf(x)); }

__device__ __forceinline__ void mma_tf32(float* c, const uint32_t* a, const uint32_t* b) {
    asm volatile(
        "mma.sync.aligned.m16n8k8.row.col.f32.tf32.tf32.f32 "
        "{%0,%1,%2,%3}, {%4,%5,%6,%7}, {%8,%9}, {%0,%1,%2,%3};\n"
        : "+f"(c[0]), "+f"(c[1]), "+f"(c[2]), "+f"(c[3])
        : "r"(a[0]), "r"(a[1]), "r"(a[2]), "r"(a[3]), "r"(b[0]), "r"(b[1]));
}

__device__ __forceinline__ float sigm(float x) {
    float e = __expf(-x);
    return __fdividef(1.0f, 1.0f + e);
}

// ---------------------------------------------------------------------------
// NT GEMM via tf32 MMA:  C[m,n] = sum_k X[m,k] * W[n,k] + bias[n]
// Block 128x128, BK=32, 8 warps (2x4), warp tile 64x32, double-buffered smem.
// smem layout k-major with leading stride 136 (== 8 mod 32 -> conflict-free frags)
// ---------------------------------------------------------------------------
#define GBM 128
#define GBN 128
#define GBK 32
#define GLD 136
#define GEMM_SMEM (2 * 2 * GBK * GLD * 4)   // 69632 B

__global__ void __launch_bounds__(256, 2) gemm_tf32_kernel(
    const float* __restrict__ X, const float* __restrict__ W,
    const float* __restrict__ bias, float* __restrict__ C,
    int K, int N)
{
    extern __shared__ uint32_t sm[];
    uint32_t* As = sm;                    // [2][GBK][GLD]
    uint32_t* Bs = sm + 2 * GBK * GLD;    // [2][GBK][GLD]

    const int tid = threadIdx.x;
    const int lane = tid & 31, wid = tid >> 5;
    const int g = lane >> 2, tig = lane & 3;
    const int warp_m = wid >> 2, warp_n = wid & 3;   // 2 x 4
    const int m0 = blockIdx.y * GBM, n0 = blockIdx.x * GBN;

    float acc[4][4][4];
#pragma unroll
    for (int i = 0; i < 4; i++)
#pragma unroll
        for (int j = 0; j < 4; j++)
#pragma unroll
            for (int r = 0; r < 4; r++) acc[i][j][r] = 0.f;

    float4 ra[4], rb[4];
    // prefetch chunk 0
#pragma unroll
    for (int i = 0; i < 4; i++) {
        int idx = tid + i * 256, row = idx >> 3, c4 = idx & 7;
        ra[i] = *(const float4*)&X[(size_t)(m0 + row) * K + c4 * 4];
        rb[i] = *(const float4*)&W[(size_t)(n0 + row) * K + c4 * 4];
    }
#pragma unroll
    for (int i = 0; i < 4; i++) {
        int idx = tid + i * 256, row = idx >> 3, c4 = idx & 7;
        As[(c4 * 4 + 0) * GLD + row] = f2tf(ra[i].x);
        As[(c4 * 4 + 1) * GLD + row] = f2tf(ra[i].y);
        As[(c4 * 4 + 2) * GLD + row] = f2tf(ra[i].z);
        As[(c4 * 4 + 3) * GLD + row] = f2tf(ra[i].w);
        Bs[(c4 * 4 + 0) * GLD + row] = f2tf(rb[i].x);
        Bs[(c4 * 4 + 1) * GLD + row] = f2tf(rb[i].y);
        Bs[(c4 * 4 + 2) * GLD + row] = f2tf(rb[i].z);
        Bs[(c4 * 4 + 3) * GLD + row] = f2tf(rb[i].w);
    }

    const int nk = K / GBK;
    for (int kc = 0; kc < nk; kc++) {
        __syncthreads();
        const int buf = kc & 1;
        const uint32_t* Ab = As + buf * GBK * GLD;
        const uint32_t* Bb = Bs + buf * GBK * GLD;

        if (kc + 1 < nk) {
            int k0n = (kc + 1) * GBK;
#pragma unroll
            for (int i = 0; i < 4; i++) {
                int idx = tid + i * 256, row = idx >> 3, c4 = idx & 7;
                ra[i] = *(const float4*)&X[(size_t)(m0 + row) * K + k0n + c4 * 4];
                rb[i] = *(const float4*)&W[(size_t)(n0 + row) * K + k0n + c4 * 4];
            }
        }

#pragma unroll
        for (int kk = 0; kk < 4; kk++) {
            uint32_t af[4][4], bf[4][2];
#pragma unroll
            for (int i = 0; i < 4; i++) {
                int rbm = warp_m * 64 + i * 16;
                af[i][0] = Ab[(kk * 8 + tig) * GLD + rbm + g];
                af[i][1] = Ab[(kk * 8 + tig) * GLD + rbm + g + 8];
                af[i][2] = Ab[(kk * 8 + tig + 4) * GLD + rbm + g];
                af[i][3] = Ab[(kk * 8 + tig + 4) * GLD + rbm + g + 8];
            }
#pragma unroll
            for (int j = 0; j < 4; j++) {
                int cb = warp_n * 32 + j * 8;
                bf[j][0] = Bb[(kk * 8 + tig) * GLD + cb + g];
                bf[j][1] = Bb[(kk * 8 + tig + 4) * GLD + cb + g];
            }
#pragma unroll
            for (int i = 0; i < 4; i++)
#pragma unroll
                for (int j = 0; j < 4; j++) mma_tf32(acc[i][j], af[i], bf[j]);
        }

        if (kc + 1 < nk) {
            uint32_t* An = As + (buf ^ 1) * GBK * GLD;
            uint32_t* Bn = Bs + (buf ^ 1) * GBK * GLD;
#pragma unroll
            for (int i = 0; i < 4; i++) {
                int idx = tid + i * 256, row = idx >> 3, c4 = idx & 7;
                An[(c4 * 4 + 0) * GLD + row] = f2tf(ra[i].x);
                An[(c4 * 4 + 1) * GLD + row] = f2tf(ra[i].y);
                An[(c4 * 4 + 2) * GLD + row] = f2tf(ra[i].z);
                An[(c4 * 4 + 3) * GLD + row] = f2tf(ra[i].w);
                Bn[(c4 * 4 + 0) * GLD + row] = f2tf(rb[i].x);
                Bn[(c4 * 4 + 1) * GLD + row] = f2tf(rb[i].y);
                Bn[(c4 * 4 + 2) * GLD + row] = f2tf(rb[i].z);
                Bn[(c4 * 4 + 3) * GLD + row] = f2tf(rb[i].w);
            }
        }
    }

    // Epilogue + bias
#pragma unroll
    for (int i = 0; i < 4; i++) {
        int rbase = m0 + warp_m * 64 + i * 16 + g;
#pragma unroll
        for (int j = 0; j < 4; j++) {
            int cbase = n0 + warp_n * 32 + j * 8 + 2 * tig;
            float b0v = bias[cbase], b1v = bias[cbase + 1];
            float2 v0 = make_float2(acc[i][j][0] + b0v, acc[i][j][1] + b1v);
            float2 v1 = make_float2(acc[i][j][2] + b0v, acc[i][j][3] + b1v);
            *(float2*)&C[(size_t)rbase * N + cbase] = v0;
            *(float2*)&C[(size_t)(rbase + 8) * N + cbase] = v1;
        }
    }
}

// ---------------------------------------------------------------------------
// Fused sigmoid attention via tf32 MMA.
// grid = (8 t-tiles of 128, 64 bh). 8 warps (4x2), warp tile 32x32.
// smem: Qs[64][136] (d-major tf32), Ks[64][72] (d-major tf32),
//       Vs[64][72] ([s][d] tf32), Ss[128][72] ([t][s] fp32/tf32-rounded)
// ---------------------------------------------------------------------------
#define ALDQ 136
#define ALDS 72
#define ATTN_SMEM ((64*ALDQ + 64*ALDS + 64*ALDS + 128*ALDS) * 4)  // 108544 B

__global__ void __launch_bounds__(256, 2) attn_tf32_kernel(
    const float* __restrict__ q, const float* __restrict__ k,
    const float* __restrict__ v, float* __restrict__ o,
    float* __restrict__ attn)
{
    extern __shared__ uint32_t sm[];
    uint32_t* Qs = sm;                          // [64][136]
    uint32_t* Ks = Qs + 64 * ALDQ;              // [64][72]
    uint32_t* Vs = Ks + 64 * ALDS;              // [64][72]
    float*    Ss = (float*)(Vs + 64 * ALDS);    // [128][72]

    const int tid = threadIdx.x;
    const int lane = tid & 31, wid = tid >> 5;
    const int g = lane >> 2, tig = lane & 3;
    const int warp_m = wid >> 1, warp_n = wid & 1;   // 4 x 2
    const int t0 = blockIdx.x * 128;
    const int bh = blockIdx.y;
    const int b = bh >> 4, h = bh & 15;
    const size_t hoff = (size_t)h * HDIM;

    // Load + scale + convert Q tile [128 x 64] -> Qs[d][t]
#pragma unroll
    for (int i = 0; i < 8; i++) {
        int idx = tid + i * 256, t = idx >> 4, d4 = idx & 15;
        float4 qv = *(const float4*)&q[((size_t)(t0 + t) * BSZ + b) * EMBED + hoff + d4 * 4];
        Qs[(d4 * 4 + 0) * ALDQ + t] = f2tf(qv.x * SCALE);
        Qs[(d4 * 4 + 1) * ALDQ + t] = f2tf(qv.y * SCALE);
        Qs[(d4 * 4 + 2) * ALDQ + t] = f2tf(qv.z * SCALE);
        Qs[(d4 * 4 + 3) * ALDQ + t] = f2tf(qv.w * SCALE);
    }

    float acc_o[2][4][4];
#pragma unroll
    for (int i = 0; i < 2; i++)
#pragma unroll
        for (int j = 0; j < 4; j++)
#pragma unroll
            for (int r = 0; r < 4; r++) acc_o[i][j][r] = 0.f;

    for (int s0 = 0; s0 < TLEN; s0 += 64) {
        __syncthreads();   // prev chunk's S·V done with Ks/Vs/Ss
        // Load K,V chunk [64 x 64]
#pragma unroll
        for (int i = 0; i < 4; i++) {
            int idx = tid + i * 256, s = idx >> 4, d4 = idx & 15;
            size_t go = ((size_t)(s0 + s) * BSZ + b) * EMBED + hoff + d4 * 4;
            float4 kv = *(const float4*)&k[go];
            Ks[(d4 * 4 + 0) * ALDS + s] = f2tf(kv.x);
            Ks[(d4 * 4 + 1) * ALDS + s] = f2tf(kv.y);
            Ks[(d4 * 4 + 2) * ALDS + s] = f2tf(kv.z);
            Ks[(d4 * 4 + 3) * ALDS + s] = f2tf(kv.w);
            float4 vv = *(const float4*)&v[go];
            uint4 vt = make_uint4(f2tf(vv.x), f2tf(vv.y), f2tf(vv.z), f2tf(vv.w));
            *(uint4*)&Vs[(size_t)s * ALDS + d4 * 4] = vt;
        }
        __syncthreads();

        // S = Q K^T  (M=128 t, N=64 s, K=64 d)
        float accs[2][4][4];
#pragma unroll
        for (int i = 0; i < 2; i++)
#pragma unroll
            for (int j = 0; j < 4; j++)
#pragma unroll
                for (int r = 0; r < 4; r++) accs[i][j][r] = 0.f;

#pragma unroll
        for (int kk = 0; kk < 8; kk++) {
            uint32_t af[2][4], bf[4][2];
#pragma unroll
            for (int i = 0; i < 2; i++) {
                int rbm = warp_m * 32 + i * 16;
                af[i][0] = Qs[(kk * 8 + tig) * ALDQ + rbm + g];
                af[i][1] = Qs[(kk * 8 + tig) * ALDQ + rbm + g + 8];
                af[i][2] = Qs[(kk * 8 + tig + 4) * ALDQ + rbm + g];
                af[i][3] = Qs[(kk * 8 + tig + 4) * ALDQ + rbm + g + 8];
            }
#pragma unroll
            for (int j = 0; j < 4; j++) {
                int cb = warp_n * 32 + j * 8;
                bf[j][0] = Ks[(kk * 8 + tig) * ALDS + cb + g];
                bf[j][1] = Ks[(kk * 8 + tig + 4) * ALDS + cb + g];
            }
#pragma unroll
            for (int i = 0; i < 2; i++)
#pragma unroll
                for (int j = 0; j < 4; j++) mma_tf32(accs[i][j], af[i], bf[j]);
        }

        // sigmoid -> Ss (tf32-rounded so it can feed the next MMA)
#pragma unroll
        for (int i = 0; i < 2; i++) {
            int rbm = warp_m * 32 + i * 16 + g;
#pragma unroll
            for (int j = 0; j < 4; j++) {
                int cb = warp_n * 32 + j * 8 + 2 * tig;
                float2 v0 = make_float2(tf32r(sigm(accs[i][j][0])), tf32r(sigm(accs[i][j][1])));
                float2 v1 = make_float2(tf32r(sigm(accs[i][j][2])), tf32r(sigm(accs[i][j][3])));
                *(float2*)&Ss[rbm * ALDS + cb] = v0;
                *(float2*)&Ss[(rbm + 8) * ALDS + cb] = v1;
            }
        }
        __syncthreads();

        // Write S tile to gmem attn (coalesced float4 rows)
        {
            size_t base = ((size_t)bh * TLEN + t0) * TLEN + s0;
#pragma unroll
            for (int i = 0; i < 8; i++) {
                int idx = tid + i * 256, t = idx >> 4, s4 = idx & 15;
                *(float4*)&attn[base + (size_t)t * TLEN + s4 * 4] =
                    *(float4*)&Ss[t * ALDS + s4 * 4];
            }
        }

        // O += S * V  (M=128 t, N=64 d, K=64 s)
#pragma unroll
        for (int kk = 0; kk < 8; kk++) {
            uint32_t af[2][4], bf[4][2];
#pragma unroll
            for (int i = 0; i < 2; i++) {
                int rbm = warp_m * 32 + i * 16;
                af[i][0] = __float_as_uint(Ss[(rbm + g) * ALDS + kk * 8 + tig]);
                af[i][1] = __float_as_uint(Ss[(rbm + g + 8) * ALDS + kk * 8 + tig]);
                af[i][2] = __float_as_uint(Ss[(rbm + g) * ALDS + kk * 8 + tig + 4]);
                af[i][3] = __float_as_uint(Ss[(rbm + g + 8) * ALDS + kk * 8 + tig + 4]);
            }
#pragma unroll
            for (int j = 0; j < 4; j++) {
                int cb = warp_n * 32 + j * 8;
                bf[j][0] = Vs[(kk * 8 + tig) * ALDS + cb + g];
                bf[j][1] = Vs[(kk * 8 + tig + 4) * ALDS + cb + g];
            }
#pragma unroll
            for (int i = 0; i < 2; i++)
#pragma unroll
                for (int j = 0; j < 4; j++) mma_tf32(acc_o[i][j], af[i], bf[j]);
        }
    }

    // Write O tile
#pragma unroll
    for (int i = 0; i < 2; i++) {
        int t = t0 + warp_m * 32 + i * 16 + g;
#pragma unroll
        for (int j = 0; j < 4; j++) {
            int d = warp_n * 32 + j * 8 + 2 * tig;
            *(float2*)&o[((size_t)t * BSZ + b) * EMBED + hoff + d] =
                make_float2(acc_o[i][j][0], acc_o[i][j][1]);
            *(float2*)&o[((size_t)(t + 8) * BSZ + b) * EMBED + hoff + d] =
                make_float2(acc_o[i][j][2], acc_o[i][j][3]);
        }
    }
}

// ---------------------------------------------------------------------------
// Launch
// ---------------------------------------------------------------------------
extern "C" void kernel_launch(void* const* d_in, const int* in_sizes, int n_in,
                              void* d_out, int out_size)
{
    const float* query = (const float*)d_in[0];
    const float* keyt  = (const float*)d_in[1];
    const float* value = (const float*)d_in[2];
    const float* w_in  = (const float*)d_in[3];   // [3E, E]
    const float* b_in  = (const float*)d_in[4];   // [3E]
    const float* w_out = (const float*)d_in[5];   // [E, E]
    const float* b_out = (const float*)d_in[6];   // [E]

    float* out  = (float*)d_out;                               // attn_output [T,B,E]
    float* attn = out + (size_t)TLEN * BSZ * EMBED;            // attn [B*H,T,T]

    float *q, *k, *v, *o;
    cudaGetSymbolAddress((void**)&q, g_q);
    cudaGetSymbolAddress((void**)&k, g_k);
    cudaGetSymbolAddress((void**)&v, g_v);
    cudaGetSymbolAddress((void**)&o, g_o);

    static bool attr_done = false;
    if (!attr_done) {
        cudaFuncSetAttribute(gemm_tf32_kernel, cudaFuncAttributeMaxDynamicSharedMemorySize, GEMM_SMEM);
        cudaFuncSetAttribute(attn_tf32_kernel, cudaFuncAttributeMaxDynamicSharedMemorySize, ATTN_SMEM);
        attr_done = true;
    }

    dim3 gblk(256);
    dim3 ggrid(EMBED / GBN, MROWS / GBM);   // (8, 32)

    gemm_tf32_kernel<<<ggrid, gblk, GEMM_SMEM>>>(query, w_in, b_in, q, EMBED, EMBED);
    gemm_tf32_kernel<<<ggrid, gblk, GEMM_SMEM>>>(keyt,  w_in + (size_t)EMBED * EMBED, b_in + EMBED, k, EMBED, EMBED);
    gemm_tf32_kernel<<<ggrid, gblk, GEMM_SMEM>>>(value, w_in + (size_t)2 * EMBED * EMBED, b_in + 2 * EMBED, v, EMBED, EMBED);

    attn_tf32_kernel<<<dim3(TLEN / 128, BSZ * NHEAD), 256, ATTN_SMEM>>>(q, k, v, o, attn);

    gemm_tf32_kernel<<<ggrid, gblk, GEMM_SMEM>>>(o, w_out, b_out, out, EMBED, EMBED);
}

// round 6
// speedup vs baseline: 5.0434x; 2.4304x over previous
#include <cuda_runtime.h>
#include <cuda_fp16.h>
#include <cstdint>

#define EMBED 1024
#define NHEAD 16
#define HDIM  64
#define TLEN  1024
#define BSZ   4
#define MROWS (TLEN*BSZ)          // 4096
#define SCALE 0.03125f            // 1/sqrt(1024)

// Scratch (half precision: mantissa identical to tf32, half the bytes)
__device__ __half g_q[(size_t)MROWS * EMBED];
__device__ __half g_k[(size_t)MROWS * EMBED];
__device__ __half g_v[(size_t)MROWS * EMBED];
__device__ __half g_o[(size_t)MROWS * EMBED];

// ---------------------------------------------------------------------------
// helpers
// ---------------------------------------------------------------------------
__device__ __forceinline__ uint32_t smem_to_u32(const void* p) {
    uint32_t a;
    asm("{ .reg .u64 t; cvta.to.shared.u64 t, %1; cvt.u32.u64 %0, t; }" : "=r"(a) : "l"(p));
    return a;
}
__device__ __forceinline__ uint32_t h2u(__half2 h) { return *reinterpret_cast<uint32_t*>(&h); }

__device__ __forceinline__ void mma_f16(float* c, const uint32_t* a, const uint32_t* b) {
    asm volatile(
        "mma.sync.aligned.m16n8k16.row.col.f32.f16.f16.f32 "
        "{%0,%1,%2,%3}, {%4,%5,%6,%7}, {%8,%9}, {%0,%1,%2,%3};\n"
        : "+f"(c[0]), "+f"(c[1]), "+f"(c[2]), "+f"(c[3])
        : "r"(a[0]), "r"(a[1]), "r"(a[2]), "r"(a[3]), "r"(b[0]), "r"(b[1]));
}
__device__ __forceinline__ void ldm_x4_trans(uint32_t* r, uint32_t addr) {
    asm volatile("ldmatrix.sync.aligned.m8n8.x4.trans.shared.b16 {%0,%1,%2,%3}, [%4];"
        : "=r"(r[0]), "=r"(r[1]), "=r"(r[2]), "=r"(r[3]) : "r"(addr));
}
__device__ __forceinline__ float sigm(float x) {
    float e = __expf(-x);
    return __fdividef(1.0f, 1.0f + e);
}

// ---------------------------------------------------------------------------
// NT GEMM via fp16 MMA (fp32 accum):  C[m,n] = sum_k X[m,k]*W[n,k] + bias[n]
// Block 128x128, BK=32, 8 warps (2x4), warp tile 64x32, double-buffered smem.
// Smem half layout [row][40] (pad 8 halves -> conflict-free fragment LDS).
// XH: X is half. OH: C output half.
// ---------------------------------------------------------------------------
#define GLDH 40

template<int XH, int OH>
__global__ void __launch_bounds__(256, 2) gemm_h_kernel(
    const void* __restrict__ Xv, const float* __restrict__ W,
    const float* __restrict__ bias, void* __restrict__ Cv, int K, int N)
{
    __shared__ __half As[2][128][GLDH];
    __shared__ __half Bs[2][128][GLDH];

    const float*  Xf = (const float*)Xv;
    const __half* Xh = (const __half*)Xv;

    const int tid = threadIdx.x;
    const int lane = tid & 31, wid = tid >> 5;
    const int g = lane >> 2, tig = lane & 3;
    const int warp_m = wid >> 2, warp_n = wid & 3;   // 2 x 4
    const int m0 = blockIdx.y * 128, n0 = blockIdx.x * 128;

    float acc[4][4][4];
#pragma unroll
    for (int i = 0; i < 4; i++)
#pragma unroll
        for (int j = 0; j < 4; j++)
#pragma unroll
            for (int r = 0; r < 4; r++) acc[i][j][r] = 0.f;

    // staging coords: idx -> row (0..127), col4 (0..7) covering 32 k-cols
    int srow[4], scol[4];
#pragma unroll
    for (int i = 0; i < 4; i++) {
        int idx = tid + i * 256;
        srow[i] = idx >> 3; scol[i] = idx & 7;
    }

    uint2 rah[4]; float4 raf[4], rbf[4];
#pragma unroll
    for (int i = 0; i < 4; i++) {
        if (XH) rah[i] = *(const uint2*)&Xh[(size_t)(m0 + srow[i]) * K + scol[i] * 4];
        else    raf[i] = *(const float4*)&Xf[(size_t)(m0 + srow[i]) * K + scol[i] * 4];
        rbf[i] = *(const float4*)&W[(size_t)(n0 + srow[i]) * K + scol[i] * 4];
    }
#pragma unroll
    for (int i = 0; i < 4; i++) {
        if (XH) *(uint2*)&As[0][srow[i]][scol[i] * 4] = rah[i];
        else {
            __half2 h0 = __floats2half2_rn(raf[i].x, raf[i].y);
            __half2 h1 = __floats2half2_rn(raf[i].z, raf[i].w);
            *(uint2*)&As[0][srow[i]][scol[i] * 4] = make_uint2(h2u(h0), h2u(h1));
        }
        __half2 b0 = __floats2half2_rn(rbf[i].x, rbf[i].y);
        __half2 b1 = __floats2half2_rn(rbf[i].z, rbf[i].w);
        *(uint2*)&Bs[0][srow[i]][scol[i] * 4] = make_uint2(h2u(b0), h2u(b1));
    }

    const int nk = K / 32;
    for (int kc = 0; kc < nk; kc++) {
        __syncthreads();
        const int buf = kc & 1;

        if (kc + 1 < nk) {
            int k0n = (kc + 1) * 32;
#pragma unroll
            for (int i = 0; i < 4; i++) {
                if (XH) rah[i] = *(const uint2*)&Xh[(size_t)(m0 + srow[i]) * K + k0n + scol[i] * 4];
                else    raf[i] = *(const float4*)&Xf[(size_t)(m0 + srow[i]) * K + k0n + scol[i] * 4];
                rbf[i] = *(const float4*)&W[(size_t)(n0 + srow[i]) * K + k0n + scol[i] * 4];
            }
        }

#pragma unroll
        for (int kk = 0; kk < 2; kk++) {
            const int kb = kk * 16;
            uint32_t af[4][4], bf[4][2];
#pragma unroll
            for (int i = 0; i < 4; i++) {
                int rm = warp_m * 64 + i * 16;
                af[i][0] = *(const uint32_t*)&As[buf][rm + g][kb + 2 * tig];
                af[i][1] = *(const uint32_t*)&As[buf][rm + g + 8][kb + 2 * tig];
                af[i][2] = *(const uint32_t*)&As[buf][rm + g][kb + 2 * tig + 8];
                af[i][3] = *(const uint32_t*)&As[buf][rm + g + 8][kb + 2 * tig + 8];
            }
#pragma unroll
            for (int j = 0; j < 4; j++) {
                int rn = warp_n * 32 + j * 8 + g;
                bf[j][0] = *(const uint32_t*)&Bs[buf][rn][kb + 2 * tig];
                bf[j][1] = *(const uint32_t*)&Bs[buf][rn][kb + 2 * tig + 8];
            }
#pragma unroll
            for (int i = 0; i < 4; i++)
#pragma unroll
                for (int j = 0; j < 4; j++) mma_f16(acc[i][j], af[i], bf[j]);
        }

        if (kc + 1 < nk) {
            const int nb = buf ^ 1;
#pragma unroll
            for (int i = 0; i < 4; i++) {
                if (XH) *(uint2*)&As[nb][srow[i]][scol[i] * 4] = rah[i];
                else {
                    __half2 h0 = __floats2half2_rn(raf[i].x, raf[i].y);
                    __half2 h1 = __floats2half2_rn(raf[i].z, raf[i].w);
                    *(uint2*)&As[nb][srow[i]][scol[i] * 4] = make_uint2(h2u(h0), h2u(h1));
                }
                __half2 b0 = __floats2half2_rn(rbf[i].x, rbf[i].y);
                __half2 b1 = __floats2half2_rn(rbf[i].z, rbf[i].w);
                *(uint2*)&Bs[nb][srow[i]][scol[i] * 4] = make_uint2(h2u(b0), h2u(b1));
            }
        }
    }

    // Epilogue + bias
#pragma unroll
    for (int i = 0; i < 4; i++) {
#pragma unroll
        for (int j = 0; j < 4; j++) {
            int m = m0 + warp_m * 64 + i * 16 + g;
            int n = n0 + warp_n * 32 + j * 8 + 2 * tig;
            float b0v = bias[n], b1v = bias[n + 1];
            float c0 = acc[i][j][0] + b0v, c1 = acc[i][j][1] + b1v;
            float c2 = acc[i][j][2] + b0v, c3 = acc[i][j][3] + b1v;
            if (OH) {
                __half* C = (__half*)Cv;
                *(__half2*)&C[(size_t)m * N + n] = __floats2half2_rn(c0, c1);
                *(__half2*)&C[(size_t)(m + 8) * N + n] = __floats2half2_rn(c2, c3);
            } else {
                float* C = (float*)Cv;
                *(float2*)&C[(size_t)m * N + n] = make_float2(c0, c1);
                *(float2*)&C[(size_t)(m + 8) * N + n] = make_float2(c2, c3);
            }
        }
    }
}

// ---------------------------------------------------------------------------
// Flash-style fp16 sigmoid attention.
// grid (8, 64): 128 t-rows per CTA, 8 warps, warp tile 16t x 64s x 64d.
// Q fragments register-resident for whole kernel. S stays in registers:
// sigmoid(fp32 acc) -> gmem attn write (stcs) -> half2 pack = A-frag of S*V.
// Smem: Ks[64][72], Vs[64][72] half (pad 8 -> conflict-free).
// ---------------------------------------------------------------------------
#define ALD 72

__global__ void __launch_bounds__(256, 2) attn_h_kernel(
    const __half* __restrict__ q, const __half* __restrict__ k,
    const __half* __restrict__ v, __half* __restrict__ o,
    float* __restrict__ attn)
{
    __shared__ __half Ks[64][ALD];
    __shared__ __half Vs[64][ALD];

    const int tid = threadIdx.x;
    const int lane = tid & 31, wid = tid >> 5;
    const int g = lane >> 2, tig = lane & 3;
    const int t0 = blockIdx.x * 128;
    const int bh = blockIdx.y;
    const int b = bh >> 4, h = bh & 15;
    const size_t hoff = (size_t)h * HDIM;
    const int tw = t0 + wid * 16;               // warp's first t-row

    const uint32_t vs_base = smem_to_u32(&Vs[0][0]);

    // Q fragments: 4 k16-tiles x 4 regs, scaled by 1/32 (exact in fp16)
    const __half2 hs = __floats2half2_rn(SCALE, SCALE);
    uint32_t qf[4][4];
#pragma unroll
    for (int kt = 0; kt < 4; kt++) {
        size_t r0 = ((size_t)(tw + g) * BSZ + b) * EMBED + hoff + kt * 16 + 2 * tig;
        size_t r1 = ((size_t)(tw + g + 8) * BSZ + b) * EMBED + hoff + kt * 16 + 2 * tig;
        qf[kt][0] = h2u(__hmul2(*(const __half2*)&q[r0], hs));
        qf[kt][1] = h2u(__hmul2(*(const __half2*)&q[r1], hs));
        qf[kt][2] = h2u(__hmul2(*(const __half2*)&q[r0 + 8], hs));
        qf[kt][3] = h2u(__hmul2(*(const __half2*)&q[r1 + 8], hs));
    }

    float oacc[8][4];
#pragma unroll
    for (int j = 0; j < 8; j++)
#pragma unroll
        for (int r = 0; r < 4; r++) oacc[j][r] = 0.f;

    const int srow = tid >> 2, sseg = tid & 3;   // staging: 4 threads/row

    for (int s0 = 0; s0 < TLEN; s0 += 64) {
        __syncthreads();
        {
            size_t gro = ((size_t)(s0 + srow) * BSZ + b) * EMBED + hoff + sseg * 16;
            uint4 k0 = *(const uint4*)&k[gro];
            uint4 k1 = *(const uint4*)&k[gro + 8];
            uint4 v0 = *(const uint4*)&v[gro];
            uint4 v1 = *(const uint4*)&v[gro + 8];
            *(uint4*)&Ks[srow][sseg * 16] = k0;
            *(uint4*)&Ks[srow][sseg * 16 + 8] = k1;
            *(uint4*)&Vs[srow][sseg * 16] = v0;
            *(uint4*)&Vs[srow][sseg * 16 + 8] = v1;
        }
        __syncthreads();

        // ---- S = Q K^T : 8 n-tiles (s), 4 k-tiles (d) ----
        float sacc[8][4];
#pragma unroll
        for (int j = 0; j < 8; j++)
#pragma unroll
            for (int r = 0; r < 4; r++) sacc[j][r] = 0.f;

#pragma unroll
        for (int kt = 0; kt < 4; kt++) {
            uint32_t kb[8][2];
#pragma unroll
            for (int j = 0; j < 8; j++) {
                kb[j][0] = *(const uint32_t*)&Ks[j * 8 + g][kt * 16 + 2 * tig];
                kb[j][1] = *(const uint32_t*)&Ks[j * 8 + g][kt * 16 + 2 * tig + 8];
            }
#pragma unroll
            for (int j = 0; j < 8; j++) mma_f16(sacc[j], qf[kt], kb[j]);
        }

        // ---- sigmoid -> gmem attn + half2 pack (== A-frag of S*V) ----
        uint32_t sf[8][2];
        {
            size_t abase = ((size_t)bh * TLEN + tw) * TLEN + s0;
#pragma unroll
            for (int j = 0; j < 8; j++) {
                float v0 = sigm(sacc[j][0]), v1 = sigm(sacc[j][1]);
                float v2 = sigm(sacc[j][2]), v3 = sigm(sacc[j][3]);
                size_t c = abase + (size_t)g * TLEN + j * 8 + 2 * tig;
                __stcs((float2*)&attn[c], make_float2(v0, v1));
                __stcs((float2*)&attn[c + 8 * TLEN], make_float2(v2, v3));
                sf[j][0] = h2u(__floats2half2_rn(v0, v1));
                sf[j][1] = h2u(__floats2half2_rn(v2, v3));
            }
        }

        // ---- O += S * V : A from sf regs, B via ldmatrix.trans ----
#pragma unroll
        for (int kt = 0; kt < 4; kt++) {
            uint32_t af[4] = { sf[2 * kt][0], sf[2 * kt][1], sf[2 * kt + 1][0], sf[2 * kt + 1][1] };
#pragma unroll
            for (int db = 0; db < 4; db++) {
                // ldmatrix x4: tiles (s 0-7 / 8-15) x (d +0 / +8)
                int tsel = lane >> 3, r = lane & 7;
                int sr = kt * 16 + (tsel & 1) * 8 + r;
                int dc = db * 16 + (tsel >> 1) * 8;
                uint32_t addr = vs_base + (uint32_t)(sr * ALD + dc) * 2;
                uint32_t vr[4];
                ldm_x4_trans(vr, addr);
                mma_f16(oacc[2 * db], af, vr);
                mma_f16(oacc[2 * db + 1], af, vr + 2);
            }
        }
    }

    // Write O (half)
#pragma unroll
    for (int j = 0; j < 8; j++) {
        size_t r0 = ((size_t)(tw + g) * BSZ + b) * EMBED + hoff + j * 8 + 2 * tig;
        size_t r1 = ((size_t)(tw + g + 8) * BSZ + b) * EMBED + hoff + j * 8 + 2 * tig;
        *(__half2*)&o[r0] = __floats2half2_rn(oacc[j][0], oacc[j][1]);
        *(__half2*)&o[r1] = __floats2half2_rn(oacc[j][2], oacc[j][3]);
    }
}

// ---------------------------------------------------------------------------
// Launch
// ---------------------------------------------------------------------------
extern "C" void kernel_launch(void* const* d_in, const int* in_sizes, int n_in,
                              void* d_out, int out_size)
{
    const float* query = (const float*)d_in[0];
    const float* keyt  = (const float*)d_in[1];
    const float* value = (const float*)d_in[2];
    const float* w_in  = (const float*)d_in[3];   // [3E, E]
    const float* b_in  = (const float*)d_in[4];   // [3E]
    const float* w_out = (const float*)d_in[5];   // [E, E]
    const float* b_out = (const float*)d_in[6];   // [E]

    float* out  = (float*)d_out;                               // attn_output [T,B,E]
    float* attn = out + (size_t)TLEN * BSZ * EMBED;            // attn [B*H,T,T]

    __half *q, *k, *v, *o;
    cudaGetSymbolAddress((void**)&q, g_q);
    cudaGetSymbolAddress((void**)&k, g_k);
    cudaGetSymbolAddress((void**)&v, g_v);
    cudaGetSymbolAddress((void**)&o, g_o);

    dim3 gblk(256);
    dim3 ggrid(EMBED / 128, MROWS / 128);   // (8, 32)

    // QKV projections: float in, half out
    gemm_h_kernel<0, 1><<<ggrid, gblk>>>(query, w_in, b_in, q, EMBED, EMBED);
    gemm_h_kernel<0, 1><<<ggrid, gblk>>>(keyt,  w_in + (size_t)EMBED * EMBED, b_in + EMBED, k, EMBED, EMBED);
    gemm_h_kernel<0, 1><<<ggrid, gblk>>>(value, w_in + (size_t)2 * EMBED * EMBED, b_in + 2 * EMBED, v, EMBED, EMBED);

    // Fused attention
    attn_h_kernel<<<dim3(TLEN / 128, BSZ * NHEAD), gblk>>>(q, k, v, o, attn);

    // Output projection: half in, float out
    gemm_h_kernel<1, 0><<<ggrid, gblk>>>(o, w_out, b_out, out, EMBED, EMBED);
}

// round 7
// speedup vs baseline: 5.5444x; 1.0993x over previous
#include <cuda_runtime.h>
#include <cuda_fp16.h>
#include <cstdint>

#define EMBED 1024
#define NHEAD 16
#define HDIM  64
#define TLEN  1024
#define BSZ   4
#define MROWS (TLEN*BSZ)          // 4096
#define SCALE 0.03125f            // 1/sqrt(1024)

// Scratch (device globals; no allocation allowed)
__device__ __half g_q[(size_t)MROWS * EMBED];
__device__ __half g_k[(size_t)MROWS * EMBED];
__device__ __half g_v[(size_t)MROWS * EMBED];
__device__ __half g_o[(size_t)MROWS * EMBED];
__device__ __half g_hx[(size_t)3 * MROWS * EMBED];     // half(query|key|value)
__device__ __half g_hwi[(size_t)3 * EMBED * EMBED];    // half(w_in)
__device__ __half g_hwo[(size_t)EMBED * EMBED];        // half(w_out)

// ---------------------------------------------------------------------------
// helpers
// ---------------------------------------------------------------------------
__device__ __forceinline__ uint32_t smem_to_u32(const void* p) {
    uint32_t a;
    asm("{ .reg .u64 t; cvta.to.shared.u64 t, %1; cvt.u32.u64 %0, t; }" : "=r"(a) : "l"(p));
    return a;
}
__device__ __forceinline__ uint32_t h2u(__half2 h) { return *reinterpret_cast<uint32_t*>(&h); }

__device__ __forceinline__ void mma_f16(float* c, const uint32_t* a, const uint32_t* b) {
    asm volatile(
        "mma.sync.aligned.m16n8k16.row.col.f32.f16.f16.f32 "
        "{%0,%1,%2,%3}, {%4,%5,%6,%7}, {%8,%9}, {%0,%1,%2,%3};\n"
        : "+f"(c[0]), "+f"(c[1]), "+f"(c[2]), "+f"(c[3])
        : "r"(a[0]), "r"(a[1]), "r"(a[2]), "r"(a[3]), "r"(b[0]), "r"(b[1]));
}
__device__ __forceinline__ void ldm_x4(uint32_t* r, uint32_t addr) {
    asm volatile("ldmatrix.sync.aligned.m8n8.x4.shared.b16 {%0,%1,%2,%3}, [%4];"
        : "=r"(r[0]), "=r"(r[1]), "=r"(r[2]), "=r"(r[3]) : "r"(addr));
}
__device__ __forceinline__ void ldm_x4_trans(uint32_t* r, uint32_t addr) {
    asm volatile("ldmatrix.sync.aligned.m8n8.x4.trans.shared.b16 {%0,%1,%2,%3}, [%4];"
        : "=r"(r[0]), "=r"(r[1]), "=r"(r[2]), "=r"(r[3]) : "r"(addr));
}
__device__ __forceinline__ float sigm(float x) {
    float e = __expf(-x);
    return __fdividef(1.0f, 1.0f + e);
}

// ---------------------------------------------------------------------------
// fp32 -> fp16 convert (grid-stride over float4)
// ---------------------------------------------------------------------------
__global__ void f2h_kernel(const float* __restrict__ in, __half* __restrict__ out, int n4) {
    int i = blockIdx.x * blockDim.x + threadIdx.x;
    if (i < n4) {
        float4 v = ((const float4*)in)[i];
        ((uint2*)out)[i] = make_uint2(h2u(__floats2half2_rn(v.x, v.y)),
                                      h2u(__floats2half2_rn(v.z, v.w)));
    }
}

// ---------------------------------------------------------------------------
// NT GEMM, all-half inputs, fp16 MMA (fp32 accum):
//   C[m,n] = sum_k X[m,k]*W[n,k] + bias[n]
// Block 128x128, BK=32, 8 warps (2x4), warp tile 64x32, double-buffered smem.
// Smem [row][40] halves (80B stride -> ldmatrix conflict-free).
// Fragments via ldmatrix.x4. OH: output half.
// ---------------------------------------------------------------------------
#define GLDH 40

template<int OH>
__global__ void __launch_bounds__(256, 2) gemm_h_kernel(
    const __half* __restrict__ X, const __half* __restrict__ W,
    const float* __restrict__ bias, void* __restrict__ Cv, int K, int N)
{
    __shared__ __half As[2][128][GLDH];
    __shared__ __half Bs[2][128][GLDH];

    const int tid = threadIdx.x;
    const int lane = tid & 31, wid = tid >> 5;
    const int g = lane >> 2, tig = lane & 3;
    const int warp_m = wid >> 2, warp_n = wid & 3;   // 2 x 4
    const int m0 = blockIdx.y * 128, n0 = blockIdx.x * 128;

    float acc[4][4][4];
#pragma unroll
    for (int i = 0; i < 4; i++)
#pragma unroll
        for (int j = 0; j < 4; j++)
#pragma unroll
            for (int r = 0; r < 4; r++) acc[i][j][r] = 0.f;

    // staging: 512 uint4 slots -> 2 per thread. row = idx>>2, seg = idx&3 (8 halves)
    const int srow0 = tid >> 2, sseg = (tid & 3) * 8;
    const int srow1 = (tid + 256) >> 2;

    // ldmatrix lane offsets (in halves)
    uint32_t a_off[4], b_off[2];
#pragma unroll
    for (int i = 0; i < 4; i++)
        a_off[i] = (uint32_t)((warp_m * 64 + i * 16 + (lane & 15)) * GLDH + (lane >> 4) * 8);
#pragma unroll
    for (int jp = 0; jp < 2; jp++)
        b_off[jp] = (uint32_t)((warp_n * 32 + jp * 16 + (lane >> 4) * 8 + (lane & 7)) * GLDH
                               + ((lane >> 3) & 1) * 8);

    const uint32_t as_b[2] = { smem_to_u32(&As[0][0][0]), smem_to_u32(&As[1][0][0]) };
    const uint32_t bs_b[2] = { smem_to_u32(&Bs[0][0][0]), smem_to_u32(&Bs[1][0][0]) };

    uint4 rxa0, rxa1, rwb0, rwb1;
    rxa0 = *(const uint4*)&X[(size_t)(m0 + srow0) * K + sseg];
    rxa1 = *(const uint4*)&X[(size_t)(m0 + srow1) * K + sseg];
    rwb0 = *(const uint4*)&W[(size_t)(n0 + srow0) * K + sseg];
    rwb1 = *(const uint4*)&W[(size_t)(n0 + srow1) * K + sseg];
    *(uint4*)&As[0][srow0][sseg] = rxa0;
    *(uint4*)&As[0][srow1][sseg] = rxa1;
    *(uint4*)&Bs[0][srow0][sseg] = rwb0;
    *(uint4*)&Bs[0][srow1][sseg] = rwb1;

    const int nk = K / 32;
    for (int kc = 0; kc < nk; kc++) {
        __syncthreads();
        const int buf = kc & 1;

        if (kc + 1 < nk) {
            int k0n = (kc + 1) * 32;
            rxa0 = *(const uint4*)&X[(size_t)(m0 + srow0) * K + k0n + sseg];
            rxa1 = *(const uint4*)&X[(size_t)(m0 + srow1) * K + k0n + sseg];
            rwb0 = *(const uint4*)&W[(size_t)(n0 + srow0) * K + k0n + sseg];
            rwb1 = *(const uint4*)&W[(size_t)(n0 + srow1) * K + k0n + sseg];
        }

#pragma unroll
        for (int kk = 0; kk < 2; kk++) {
            const uint32_t kb = kk * 16;
            uint32_t af[4][4], bf[4][2];
#pragma unroll
            for (int i = 0; i < 4; i++)
                ldm_x4(af[i], as_b[buf] + (a_off[i] + kb) * 2);
#pragma unroll
            for (int jp = 0; jp < 2; jp++) {
                uint32_t t[4];
                ldm_x4(t, bs_b[buf] + (b_off[jp] + kb) * 2);
                bf[jp * 2][0] = t[0]; bf[jp * 2][1] = t[1];
                bf[jp * 2 + 1][0] = t[2]; bf[jp * 2 + 1][1] = t[3];
            }
#pragma unroll
            for (int i = 0; i < 4; i++)
#pragma unroll
                for (int j = 0; j < 4; j++) mma_f16(acc[i][j], af[i], bf[j]);
        }

        if (kc + 1 < nk) {
            const int nb = buf ^ 1;
            *(uint4*)&As[nb][srow0][sseg] = rxa0;
            *(uint4*)&As[nb][srow1][sseg] = rxa1;
            *(uint4*)&Bs[nb][srow0][sseg] = rwb0;
            *(uint4*)&Bs[nb][srow1][sseg] = rwb1;
        }
    }

    // Epilogue + bias
#pragma unroll
    for (int i = 0; i < 4; i++) {
#pragma unroll
        for (int j = 0; j < 4; j++) {
            int m = m0 + warp_m * 64 + i * 16 + g;
            int n = n0 + warp_n * 32 + j * 8 + 2 * tig;
            float b0v = bias[n], b1v = bias[n + 1];
            float c0 = acc[i][j][0] + b0v, c1 = acc[i][j][1] + b1v;
            float c2 = acc[i][j][2] + b0v, c3 = acc[i][j][3] + b1v;
            if (OH) {
                __half* C = (__half*)Cv;
                *(__half2*)&C[(size_t)m * N + n] = __floats2half2_rn(c0, c1);
                *(__half2*)&C[(size_t)(m + 8) * N + n] = __floats2half2_rn(c2, c3);
            } else {
                float* C = (float*)Cv;
                *(float2*)&C[(size_t)m * N + n] = make_float2(c0, c1);
                *(float2*)&C[(size_t)(m + 8) * N + n] = make_float2(c2, c3);
            }
        }
    }
}

// ---------------------------------------------------------------------------
// Flash-style fp16 sigmoid attention.
// grid (8, 64): 128 t-rows/CTA, 8 warps, warp tile 16t x 64s x 64d.
// Q register-resident; K frags via ldmatrix.x4; V via ldmatrix.x4.trans;
// S: sigmoid(fp32 acc) -> per-warp SMEM stage -> coalesced STG.128 to attn;
// half2 pack of S == A-frag of S*V (no smem round trip for the MMA).
// dyn smem: Ks[64][72] + Vs[64][72] half + Sst[8][16][72] float = 55296 B
// ---------------------------------------------------------------------------
#define ALD 72
#define SLD 72
#define ATTN_SMEM (64*ALD*2*2 + 8*16*SLD*4)

__global__ void __launch_bounds__(256, 2) attn_h_kernel(
    const __half* __restrict__ q, const __half* __restrict__ k,
    const __half* __restrict__ v, __half* __restrict__ o,
    float* __restrict__ attn)
{
    extern __shared__ char smraw[];
    __half* Ks = (__half*)smraw;              // [64][ALD]
    __half* Vs = Ks + 64 * ALD;               // [64][ALD]
    float*  Sst = (float*)(Vs + 64 * ALD);    // [8][16][SLD]

    const int tid = threadIdx.x;
    const int lane = tid & 31, wid = tid >> 5;
    const int g = lane >> 2, tig = lane & 3;
    const int t0 = blockIdx.x * 128;
    const int bh = blockIdx.y;
    const int b = bh >> 4, h = bh & 15;
    const size_t hoff = (size_t)h * HDIM;
    const int tw = t0 + wid * 16;

    const uint32_t ks_base = smem_to_u32(Ks);
    const uint32_t vs_base = smem_to_u32(Vs);
    float* sw = Sst + wid * 16 * SLD;

    // K-fragment ldmatrix lane offsets (halves): jp covers j-tiles {2jp, 2jp+1}
    uint32_t k_off[4];
#pragma unroll
    for (int jp = 0; jp < 4; jp++)
        k_off[jp] = (uint32_t)((jp * 16 + (lane >> 4) * 8 + (lane & 7)) * ALD
                               + ((lane >> 3) & 1) * 8);

    // Q fragments: 4 k16-tiles x 4 regs, scaled by 1/32 (exact in fp16)
    const __half2 hs = __floats2half2_rn(SCALE, SCALE);
    uint32_t qf[4][4];
#pragma unroll
    for (int kt = 0; kt < 4; kt++) {
        size_t r0 = ((size_t)(tw + g) * BSZ + b) * EMBED + hoff + kt * 16 + 2 * tig;
        size_t r1 = ((size_t)(tw + g + 8) * BSZ + b) * EMBED + hoff + kt * 16 + 2 * tig;
        qf[kt][0] = h2u(__hmul2(*(const __half2*)&q[r0], hs));
        qf[kt][1] = h2u(__hmul2(*(const __half2*)&q[r1], hs));
        qf[kt][2] = h2u(__hmul2(*(const __half2*)&q[r0 + 8], hs));
        qf[kt][3] = h2u(__hmul2(*(const __half2*)&q[r1 + 8], hs));
    }

    float oacc[8][4];
#pragma unroll
    for (int j = 0; j < 8; j++)
#pragma unroll
        for (int r = 0; r < 4; r++) oacc[j][r] = 0.f;

    const int srow = tid >> 2, sseg = tid & 3;   // K/V staging: 4 threads/row

    for (int s0 = 0; s0 < TLEN; s0 += 64) {
        __syncthreads();
        {
            size_t gro = ((size_t)(s0 + srow) * BSZ + b) * EMBED + hoff + sseg * 16;
            uint4 k0 = *(const uint4*)&k[gro];
            uint4 k1 = *(const uint4*)&k[gro + 8];
            uint4 v0 = *(const uint4*)&v[gro];
            uint4 v1 = *(const uint4*)&v[gro + 8];
            *(uint4*)&Ks[srow * ALD + sseg * 16] = k0;
            *(uint4*)&Ks[srow * ALD + sseg * 16 + 8] = k1;
            *(uint4*)&Vs[srow * ALD + sseg * 16] = v0;
            *(uint4*)&Vs[srow * ALD + sseg * 16 + 8] = v1;
        }
        __syncthreads();

        // ---- S = Q K^T : 8 n-tiles (s), 4 k-tiles (d); K frags via ldmatrix ----
        float sacc[8][4];
#pragma unroll
        for (int j = 0; j < 8; j++)
#pragma unroll
            for (int r = 0; r < 4; r++) sacc[j][r] = 0.f;

#pragma unroll
        for (int kt = 0; kt < 4; kt++) {
            uint32_t kb[8][2];
#pragma unroll
            for (int jp = 0; jp < 4; jp++) {
                uint32_t t[4];
                ldm_x4(t, ks_base + (k_off[jp] + kt * 16) * 2);
                kb[jp * 2][0] = t[0]; kb[jp * 2][1] = t[1];
                kb[jp * 2 + 1][0] = t[2]; kb[jp * 2 + 1][1] = t[3];
            }
#pragma unroll
            for (int j = 0; j < 8; j++) mma_f16(sacc[j], qf[kt], kb[j]);
        }

        // ---- sigmoid -> per-warp smem stage + half2 pack ----
        uint32_t sf[8][2];
#pragma unroll
        for (int j = 0; j < 8; j++) {
            float v0 = sigm(sacc[j][0]), v1 = sigm(sacc[j][1]);
            float v2 = sigm(sacc[j][2]), v3 = sigm(sacc[j][3]);
            *(float2*)&sw[g * SLD + j * 8 + 2 * tig] = make_float2(v0, v1);
            *(float2*)&sw[(g + 8) * SLD + j * 8 + 2 * tig] = make_float2(v2, v3);
            sf[j][0] = h2u(__floats2half2_rn(v0, v1));
            sf[j][1] = h2u(__floats2half2_rn(v2, v3));
        }
        __syncwarp();

        // ---- coalesced attn store: 16 rows x 256B, STG.128 ----
        {
            size_t abase = ((size_t)bh * TLEN + tw) * TLEN + s0;
#pragma unroll
            for (int it = 0; it < 8; it++) {
                int row = it * 2 + (lane >> 4);
                int col = (lane & 15) * 4;
                float4 val = *(float4*)&sw[row * SLD + col];
                __stcs((float4*)&attn[abase + (size_t)row * TLEN + col], val);
            }
        }

        // ---- O += S * V : A from sf regs, B via ldmatrix.trans ----
#pragma unroll
        for (int kt = 0; kt < 4; kt++) {
            uint32_t af[4] = { sf[2 * kt][0], sf[2 * kt][1], sf[2 * kt + 1][0], sf[2 * kt + 1][1] };
#pragma unroll
            for (int db = 0; db < 4; db++) {
                int tsel = lane >> 3, r = lane & 7;
                int sr = kt * 16 + (tsel & 1) * 8 + r;
                int dc = db * 16 + (tsel >> 1) * 8;
                uint32_t addr = vs_base + (uint32_t)(sr * ALD + dc) * 2;
                uint32_t vr[4];
                ldm_x4_trans(vr, addr);
                mma_f16(oacc[2 * db], af, vr);
                mma_f16(oacc[2 * db + 1], af, vr + 2);
            }
        }
    }

    // Write O (half)
#pragma unroll
    for (int j = 0; j < 8; j++) {
        size_t r0 = ((size_t)(tw + g) * BSZ + b) * EMBED + hoff + j * 8 + 2 * tig;
        size_t r1 = ((size_t)(tw + g + 8) * BSZ + b) * EMBED + hoff + j * 8 + 2 * tig;
        *(__half2*)&o[r0] = __floats2half2_rn(oacc[j][0], oacc[j][1]);
        *(__half2*)&o[r1] = __floats2half2_rn(oacc[j][2], oacc[j][3]);
    }
}

// ---------------------------------------------------------------------------
// Launch
// ---------------------------------------------------------------------------
extern "C" void kernel_launch(void* const* d_in, const int* in_sizes, int n_in,
                              void* d_out, int out_size)
{
    const float* query = (const float*)d_in[0];
    const float* keyt  = (const float*)d_in[1];
    const float* value = (const float*)d_in[2];
    const float* w_in  = (const float*)d_in[3];   // [3E, E]
    const float* b_in  = (const float*)d_in[4];   // [3E]
    const float* w_out = (const float*)d_in[5];   // [E, E]
    const float* b_out = (const float*)d_in[6];   // [E]

    float* out  = (float*)d_out;                               // attn_output [T,B,E]
    float* attn = out + (size_t)TLEN * BSZ * EMBED;            // attn [B*H,T,T]

    __half *q, *k, *v, *o, *hx, *hwi, *hwo;
    cudaGetSymbolAddress((void**)&q, g_q);
    cudaGetSymbolAddress((void**)&k, g_k);
    cudaGetSymbolAddress((void**)&v, g_v);
    cudaGetSymbolAddress((void**)&o, g_o);
    cudaGetSymbolAddress((void**)&hx, g_hx);
    cudaGetSymbolAddress((void**)&hwi, g_hwi);
    cudaGetSymbolAddress((void**)&hwo, g_hwo);

    cudaFuncSetAttribute(attn_h_kernel, cudaFuncAttributeMaxDynamicSharedMemorySize, ATTN_SMEM);

    const size_t NE = (size_t)MROWS * EMBED;       // 4M
    const size_t WE = (size_t)EMBED * EMBED;       // 1M

    // fp32 -> fp16 converts
    f2h_kernel<<<(int)(NE / 4 + 255) / 256, 256>>>(query, hx, (int)(NE / 4));
    f2h_kernel<<<(int)(NE / 4 + 255) / 256, 256>>>(keyt,  hx + NE, (int)(NE / 4));
    f2h_kernel<<<(int)(NE / 4 + 255) / 256, 256>>>(value, hx + 2 * NE, (int)(NE / 4));
    f2h_kernel<<<(int)(3 * WE / 4 + 255) / 256, 256>>>(w_in, hwi, (int)(3 * WE / 4));
    f2h_kernel<<<(int)(WE / 4 + 255) / 256, 256>>>(w_out, hwo, (int)(WE / 4));

    dim3 gblk(256);
    dim3 ggrid(EMBED / 128, MROWS / 128);   // (8, 32)

    // QKV projections (half in, half out)
    gemm_h_kernel<1><<<ggrid, gblk>>>(hx,          hwi,          b_in,             q, EMBED, EMBED);
    gemm_h_kernel<1><<<ggrid, gblk>>>(hx + NE,     hwi + WE,     b_in + EMBED,     k, EMBED, EMBED);
    gemm_h_kernel<1><<<ggrid, gblk>>>(hx + 2 * NE, hwi + 2 * WE, b_in + 2 * EMBED, v, EMBED, EMBED);

    // Fused attention
    attn_h_kernel<<<dim3(TLEN / 128, BSZ * NHEAD), gblk, ATTN_SMEM>>>(q, k, v, o, attn);

    // Output projection (half in, float out)
    gemm_h_kernel<0><<<ggrid, gblk>>>(o, hwo, b_out, out, EMBED, EMBED);
}

// round 8
// speedup vs baseline: 5.7643x; 1.0397x over previous
#include <cuda_runtime.h>
#include <cuda_fp16.h>
#include <cstdint>

#define EMBED 1024
#define NHEAD 16
#define HDIM  64
#define TLEN  1024
#define BSZ   4
#define MROWS (TLEN*BSZ)          // 4096
#define SCALE 0.03125f            // 1/sqrt(1024)

// Scratch (device globals; no allocation allowed)
__device__ __half g_q[(size_t)MROWS * EMBED];
__device__ __half g_k[(size_t)MROWS * EMBED];
__device__ __half g_v[(size_t)MROWS * EMBED];
__device__ __half g_o[(size_t)MROWS * EMBED];
__device__ __half g_hx[(size_t)3 * MROWS * EMBED];     // half(query|key|value)
__device__ __half g_hwi[(size_t)3 * EMBED * EMBED];    // half(w_in)
__device__ __half g_hwo[(size_t)EMBED * EMBED];        // half(w_out)

// ---------------------------------------------------------------------------
// helpers
// ---------------------------------------------------------------------------
__device__ __forceinline__ uint32_t smem_to_u32(const void* p) {
    uint32_t a;
    asm("{ .reg .u64 t; cvta.to.shared.u64 t, %1; cvt.u32.u64 %0, t; }" : "=r"(a) : "l"(p));
    return a;
}
__device__ __forceinline__ uint32_t h2u(__half2 h) { return *reinterpret_cast<uint32_t*>(&h); }

__device__ __forceinline__ void mma_f16(float* c, const uint32_t* a, const uint32_t* b) {
    asm volatile(
        "mma.sync.aligned.m16n8k16.row.col.f32.f16.f16.f32 "
        "{%0,%1,%2,%3}, {%4,%5,%6,%7}, {%8,%9}, {%0,%1,%2,%3};\n"
        : "+f"(c[0]), "+f"(c[1]), "+f"(c[2]), "+f"(c[3])
        : "r"(a[0]), "r"(a[1]), "r"(a[2]), "r"(a[3]), "r"(b[0]), "r"(b[1]));
}
__device__ __forceinline__ void ldm_x4(uint32_t* r, uint32_t addr) {
    asm volatile("ldmatrix.sync.aligned.m8n8.x4.shared.b16 {%0,%1,%2,%3}, [%4];"
        : "=r"(r[0]), "=r"(r[1]), "=r"(r[2]), "=r"(r[3]) : "r"(addr));
}
__device__ __forceinline__ void ldm_x4_trans(uint32_t* r, uint32_t addr) {
    asm volatile("ldmatrix.sync.aligned.m8n8.x4.trans.shared.b16 {%0,%1,%2,%3}, [%4];"
        : "=r"(r[0]), "=r"(r[1]), "=r"(r[2]), "=r"(r[3]) : "r"(addr));
}
__device__ __forceinline__ float sigm(float x) {
    float e = __expf(-x);
    return __fdividef(1.0f, 1.0f + e);
}
#define CP_ASYNC16(dst, src) \
    asm volatile("cp.async.ca.shared.global [%0], [%1], 16;" :: "r"((uint32_t)(dst)), "l"(src))
#define CP_COMMIT() asm volatile("cp.async.commit_group;" ::: "memory")
#define CP_WAIT(n)  asm volatile("cp.async.wait_group %0;" :: "n"(n) : "memory")

// ---------------------------------------------------------------------------
// fp32 -> fp16 convert. grid.z selects source; dst = out + z*n4*4 elements.
// ---------------------------------------------------------------------------
__global__ void f2h3_kernel(const float* __restrict__ a, const float* __restrict__ b,
                            const float* __restrict__ c, __half* __restrict__ out, int n4) {
    int i = blockIdx.x * blockDim.x + threadIdx.x;
    const float* src = (blockIdx.z == 0) ? a : (blockIdx.z == 1) ? b : c;
    if (i < n4) {
        float4 v = ((const float4*)src)[i];
        ((uint2*)out)[(size_t)blockIdx.z * n4 + i] =
            make_uint2(h2u(__floats2half2_rn(v.x, v.y)), h2u(__floats2half2_rn(v.z, v.w)));
    }
}
__global__ void f2h_kernel(const float* __restrict__ in, __half* __restrict__ out, int n4) {
    int i = blockIdx.x * blockDim.x + threadIdx.x;
    if (i < n4) {
        float4 v = ((const float4*)in)[i];
        ((uint2*)out)[i] = make_uint2(h2u(__floats2half2_rn(v.x, v.y)),
                                      h2u(__floats2half2_rn(v.z, v.w)));
    }
}

// ---------------------------------------------------------------------------
// NT GEMM, all-half, fp16 MMA fp32 accum, cp.async double-buffered staging.
// Block 128x128, BK=32, 8 warps (2x4), warp tile 64x32.
// grid.z batches independent GEMMs (X += z*xs, W += z*ws, bias += z*bs,
// C selected from {C0,C1,C2}[z]). OH: output half.
// ---------------------------------------------------------------------------
#define GLDH 40

template<int OH>
__global__ void __launch_bounds__(256, 2) gemm_h_kernel(
    const __half* __restrict__ Xb, const __half* __restrict__ Wb,
    const float* __restrict__ biasb,
    void* __restrict__ C0, void* __restrict__ C1, void* __restrict__ C2,
    int K, int N, long xs, long ws, long bs)
{
    __shared__ __half As[2][128][GLDH];
    __shared__ __half Bs[2][128][GLDH];

    const int z = blockIdx.z;
    const __half* X = Xb + (size_t)z * xs;
    const __half* W = Wb + (size_t)z * ws;
    const float* bias = biasb + (size_t)z * bs;
    void* Cv = (z == 0) ? C0 : (z == 1) ? C1 : C2;

    const int tid = threadIdx.x;
    const int lane = tid & 31, wid = tid >> 5;
    const int g = lane >> 2, tig = lane & 3;
    const int warp_m = wid >> 2, warp_n = wid & 3;   // 2 x 4
    const int m0 = blockIdx.y * 128, n0 = blockIdx.x * 128;

    float acc[4][4][4];
#pragma unroll
    for (int i = 0; i < 4; i++)
#pragma unroll
        for (int j = 0; j < 4; j++)
#pragma unroll
            for (int r = 0; r < 4; r++) acc[i][j][r] = 0.f;

    // staging: 512 16B-units per operand, 2 per thread
    const int srow0 = tid >> 2, srow1 = (tid + 256) >> 2;
    const int sseg = (tid & 3) * 8;                        // halves

    const uint32_t as_b[2] = { smem_to_u32(&As[0][0][0]), smem_to_u32(&As[1][0][0]) };
    const uint32_t bs_b[2] = { smem_to_u32(&Bs[0][0][0]), smem_to_u32(&Bs[1][0][0]) };

    // ldmatrix lane offsets (halves)
    uint32_t a_off[4], b_off[2];
#pragma unroll
    for (int i = 0; i < 4; i++)
        a_off[i] = (uint32_t)((warp_m * 64 + i * 16 + (lane & 15)) * GLDH + (lane >> 4) * 8);
#pragma unroll
    for (int jp = 0; jp < 2; jp++)
        b_off[jp] = (uint32_t)((warp_n * 32 + jp * 16 + (lane >> 4) * 8 + (lane & 7)) * GLDH
                               + ((lane >> 3) & 1) * 8);

    const int nk = K / 32;

    // prologue: stage chunk 0 into buf 0
    {
        CP_ASYNC16(as_b[0] + (srow0 * GLDH + sseg) * 2, &X[(size_t)(m0 + srow0) * K + sseg]);
        CP_ASYNC16(as_b[0] + (srow1 * GLDH + sseg) * 2, &X[(size_t)(m0 + srow1) * K + sseg]);
        CP_ASYNC16(bs_b[0] + (srow0 * GLDH + sseg) * 2, &W[(size_t)(n0 + srow0) * K + sseg]);
        CP_ASYNC16(bs_b[0] + (srow1 * GLDH + sseg) * 2, &W[(size_t)(n0 + srow1) * K + sseg]);
        CP_COMMIT();
    }

    for (int kc = 0; kc < nk; kc++) {
        const int buf = kc & 1;
        if (kc + 1 < nk) {
            const int nb = buf ^ 1;
            int k0n = (kc + 1) * 32;
            CP_ASYNC16(as_b[nb] + (srow0 * GLDH + sseg) * 2, &X[(size_t)(m0 + srow0) * K + k0n + sseg]);
            CP_ASYNC16(as_b[nb] + (srow1 * GLDH + sseg) * 2, &X[(size_t)(m0 + srow1) * K + k0n + sseg]);
            CP_ASYNC16(bs_b[nb] + (srow0 * GLDH + sseg) * 2, &W[(size_t)(n0 + srow0) * K + k0n + sseg]);
            CP_ASYNC16(bs_b[nb] + (srow1 * GLDH + sseg) * 2, &W[(size_t)(n0 + srow1) * K + k0n + sseg]);
            CP_COMMIT();
            CP_WAIT(1);
        } else {
            CP_WAIT(0);
        }
        __syncthreads();

#pragma unroll
        for (int kk = 0; kk < 2; kk++) {
            const uint32_t kb = kk * 16;
            uint32_t af[4][4], bf[4][2];
#pragma unroll
            for (int i = 0; i < 4; i++)
                ldm_x4(af[i], as_b[buf] + (a_off[i] + kb) * 2);
#pragma unroll
            for (int jp = 0; jp < 2; jp++) {
                uint32_t t[4];
                ldm_x4(t, bs_b[buf] + (b_off[jp] + kb) * 2);
                bf[jp * 2][0] = t[0]; bf[jp * 2][1] = t[1];
                bf[jp * 2 + 1][0] = t[2]; bf[jp * 2 + 1][1] = t[3];
            }
#pragma unroll
            for (int i = 0; i < 4; i++)
#pragma unroll
                for (int j = 0; j < 4; j++) mma_f16(acc[i][j], af[i], bf[j]);
        }
        __syncthreads();   // all warps done with buf before it is overwritten
    }

    // Epilogue + bias
#pragma unroll
    for (int i = 0; i < 4; i++) {
#pragma unroll
        for (int j = 0; j < 4; j++) {
            int m = m0 + warp_m * 64 + i * 16 + g;
            int n = n0 + warp_n * 32 + j * 8 + 2 * tig;
            float b0v = bias[n], b1v = bias[n + 1];
            float c0 = acc[i][j][0] + b0v, c1 = acc[i][j][1] + b1v;
            float c2 = acc[i][j][2] + b0v, c3 = acc[i][j][3] + b1v;
            if (OH) {
                __half* C = (__half*)Cv;
                *(__half2*)&C[(size_t)m * N + n] = __floats2half2_rn(c0, c1);
                *(__half2*)&C[(size_t)(m + 8) * N + n] = __floats2half2_rn(c2, c3);
            } else {
                float* C = (float*)Cv;
                *(float2*)&C[(size_t)m * N + n] = make_float2(c0, c1);
                *(float2*)&C[(size_t)(m + 8) * N + n] = make_float2(c2, c3);
            }
        }
    }
}

// ---------------------------------------------------------------------------
// Flash-style fp16 sigmoid attention, cp.async double-buffered K/V.
// grid (8, 64): 128 t-rows/CTA, 8 warps, warp tile 16t x 64s x 64d.
// dyn smem: K/V 2 bufs x 2 arrays x 64 x 72 halves (36864B)
//         + S stage 8 x 16 x 72 floats (36864B) = 73728 B
// ---------------------------------------------------------------------------
#define ALD 72
#define SLD 72
#define ATTN_SMEM (2 * 2 * 64 * ALD * 2 + 8 * 16 * SLD * 4)

__global__ void __launch_bounds__(256, 2) attn_h_kernel(
    const __half* __restrict__ q, const __half* __restrict__ k,
    const __half* __restrict__ v, __half* __restrict__ o,
    float* __restrict__ attn)
{
    extern __shared__ char smraw[];
    __half* KV = (__half*)smraw;                       // [2][2][64][ALD] (buf, K/V)
    float*  Sst = (float*)(KV + 2 * 2 * 64 * ALD);     // [8][16][SLD]

    const int tid = threadIdx.x;
    const int lane = tid & 31, wid = tid >> 5;
    const int g = lane >> 2, tig = lane & 3;
    const int t0 = blockIdx.x * 128;
    const int bh = blockIdx.y;
    const int b = bh >> 4, h = bh & 15;
    const size_t hoff = (size_t)h * HDIM;
    const int tw = t0 + wid * 16;

    const uint32_t kv_base = smem_to_u32(KV);
    // buffer bases (bytes): buf*2*64*ALD*2 ; V offset within buf: 64*ALD*2
    const uint32_t bufsz = 2 * 64 * ALD * 2;
    const uint32_t vofs = 64 * ALD * 2;
    float* sw = Sst + wid * 16 * SLD;

    // K-fragment ldmatrix lane offsets (halves)
    uint32_t k_off[4];
#pragma unroll
    for (int jp = 0; jp < 4; jp++)
        k_off[jp] = (uint32_t)((jp * 16 + (lane >> 4) * 8 + (lane & 7)) * ALD
                               + ((lane >> 3) & 1) * 8);
    // V-fragment (trans) lane offsets (halves), indexed [kt][db]
    const int tsel = lane >> 3, vr_ = lane & 7;

    // staging coords: 4 threads per row, 2x16B per array
    const int srow = tid >> 2, ssg = (tid & 3) * 16;    // halves

    // Q fragments, scaled
    const __half2 hs = __floats2half2_rn(SCALE, SCALE);
    uint32_t qf[4][4];
#pragma unroll
    for (int kt = 0; kt < 4; kt++) {
        size_t r0 = ((size_t)(tw + g) * BSZ + b) * EMBED + hoff + kt * 16 + 2 * tig;
        size_t r1 = ((size_t)(tw + g + 8) * BSZ + b) * EMBED + hoff + kt * 16 + 2 * tig;
        qf[kt][0] = h2u(__hmul2(*(const __half2*)&q[r0], hs));
        qf[kt][1] = h2u(__hmul2(*(const __half2*)&q[r1], hs));
        qf[kt][2] = h2u(__hmul2(*(const __half2*)&q[r0 + 8], hs));
        qf[kt][3] = h2u(__hmul2(*(const __half2*)&q[r1 + 8], hs));
    }

    float oacc[8][4];
#pragma unroll
    for (int j = 0; j < 8; j++)
#pragma unroll
        for (int r = 0; r < 4; r++) oacc[j][r] = 0.f;

    // prologue: stage chunk 0 into buf 0
    {
        size_t gro = ((size_t)srow * BSZ + b) * EMBED + hoff + ssg;
        uint32_t db = kv_base + (uint32_t)(srow * ALD + ssg) * 2;
        CP_ASYNC16(db, &k[gro]);
        CP_ASYNC16(db + 16, &k[gro + 8]);
        CP_ASYNC16(db + vofs, &v[gro]);
        CP_ASYNC16(db + vofs + 16, &v[gro + 8]);
        CP_COMMIT();
    }

    for (int ci = 0; ci < 16; ci++) {
        const int s0 = ci * 64;
        const int buf = ci & 1;
        const uint32_t kbB = kv_base + buf * bufsz;
        const uint32_t vbB = kbB + vofs;

        if (ci < 15) {
            size_t gro = ((size_t)(s0 + 64 + srow) * BSZ + b) * EMBED + hoff + ssg;
            uint32_t db = kv_base + (buf ^ 1) * bufsz + (uint32_t)(srow * ALD + ssg) * 2;
            CP_ASYNC16(db, &k[gro]);
            CP_ASYNC16(db + 16, &k[gro + 8]);
            CP_ASYNC16(db + vofs, &v[gro]);
            CP_ASYNC16(db + vofs + 16, &v[gro + 8]);
            CP_COMMIT();
            CP_WAIT(1);
        } else {
            CP_WAIT(0);
        }
        __syncthreads();

        // ---- S = Q K^T ----
        float sacc[8][4];
#pragma unroll
        for (int j = 0; j < 8; j++)
#pragma unroll
            for (int r = 0; r < 4; r++) sacc[j][r] = 0.f;

#pragma unroll
        for (int kt = 0; kt < 4; kt++) {
            uint32_t kb[8][2];
#pragma unroll
            for (int jp = 0; jp < 4; jp++) {
                uint32_t t[4];
                ldm_x4(t, kbB + (k_off[jp] + kt * 16) * 2);
                kb[jp * 2][0] = t[0]; kb[jp * 2][1] = t[1];
                kb[jp * 2 + 1][0] = t[2]; kb[jp * 2 + 1][1] = t[3];
            }
#pragma unroll
            for (int j = 0; j < 8; j++) mma_f16(sacc[j], qf[kt], kb[j]);
        }

        // ---- sigmoid -> per-warp smem stage + half2 pack ----
        uint32_t sf[8][2];
#pragma unroll
        for (int j = 0; j < 8; j++) {
            float v0 = sigm(sacc[j][0]), v1 = sigm(sacc[j][1]);
            float v2 = sigm(sacc[j][2]), v3 = sigm(sacc[j][3]);
            *(float2*)&sw[g * SLD + j * 8 + 2 * tig] = make_float2(v0, v1);
            *(float2*)&sw[(g + 8) * SLD + j * 8 + 2 * tig] = make_float2(v2, v3);
            sf[j][0] = h2u(__floats2half2_rn(v0, v1));
            sf[j][1] = h2u(__floats2half2_rn(v2, v3));
        }
        __syncwarp();

        // ---- coalesced attn store: 16 rows x 256B, STG.128 ----
        {
            size_t abase = ((size_t)bh * TLEN + tw) * TLEN + s0;
#pragma unroll
            for (int it = 0; it < 8; it++) {
                int row = it * 2 + (lane >> 4);
                int col = (lane & 15) * 4;
                float4 val = *(float4*)&sw[row * SLD + col];
                __stcs((float4*)&attn[abase + (size_t)row * TLEN + col], val);
            }
        }

        // ---- O += S * V ----
#pragma unroll
        for (int kt = 0; kt < 4; kt++) {
            uint32_t af[4] = { sf[2 * kt][0], sf[2 * kt][1], sf[2 * kt + 1][0], sf[2 * kt + 1][1] };
#pragma unroll
            for (int db = 0; db < 4; db++) {
                int sr = kt * 16 + (tsel & 1) * 8 + vr_;
                int dc = db * 16 + (tsel >> 1) * 8;
                uint32_t addr = vbB + (uint32_t)(sr * ALD + dc) * 2;
                uint32_t vr[4];
                ldm_x4_trans(vr, addr);
                mma_f16(oacc[2 * db], af, vr);
                mma_f16(oacc[2 * db + 1], af, vr + 2);
            }
        }
        __syncthreads();   // all warps done with buf before overwrite
    }

    // Write O (half)
#pragma unroll
    for (int j = 0; j < 8; j++) {
        size_t r0 = ((size_t)(tw + g) * BSZ + b) * EMBED + hoff + j * 8 + 2 * tig;
        size_t r1 = ((size_t)(tw + g + 8) * BSZ + b) * EMBED + hoff + j * 8 + 2 * tig;
        *(__half2*)&o[r0] = __floats2half2_rn(oacc[j][0], oacc[j][1]);
        *(__half2*)&o[r1] = __floats2half2_rn(oacc[j][2], oacc[j][3]);
    }
}

// ---------------------------------------------------------------------------
// Launch
// ---------------------------------------------------------------------------
extern "C" void kernel_launch(void* const* d_in, const int* in_sizes, int n_in,
                              void* d_out, int out_size)
{
    const float* query = (const float*)d_in[0];
    const float* keyt  = (const float*)d_in[1];
    const float* value = (const float*)d_in[2];
    const float* w_in  = (const float*)d_in[3];   // [3E, E]
    const float* b_in  = (const float*)d_in[4];   // [3E]
    const float* w_out = (const float*)d_in[5];   // [E, E]
    const float* b_out = (const float*)d_in[6];   // [E]

    float* out  = (float*)d_out;                               // attn_output [T,B,E]
    float* attn = out + (size_t)TLEN * BSZ * EMBED;            // attn [B*H,T,T]

    __half *q, *k, *v, *o, *hx, *hwi, *hwo;
    cudaGetSymbolAddress((void**)&q, g_q);
    cudaGetSymbolAddress((void**)&k, g_k);
    cudaGetSymbolAddress((void**)&v, g_v);
    cudaGetSymbolAddress((void**)&o, g_o);
    cudaGetSymbolAddress((void**)&hx, g_hx);
    cudaGetSymbolAddress((void**)&hwi, g_hwi);
    cudaGetSymbolAddress((void**)&hwo, g_hwo);

    cudaFuncSetAttribute(attn_h_kernel, cudaFuncAttributeMaxDynamicSharedMemorySize, ATTN_SMEM);

    const size_t NE = (size_t)MROWS * EMBED;       // 4M
    const size_t WE = (size_t)EMBED * EMBED;       // 1M

    // fp32 -> fp16 converts (batched q/k/v + weights)
    f2h3_kernel<<<dim3((int)(NE / 4 + 255) / 256, 1, 3), 256>>>(query, keyt, value, hx, (int)(NE / 4));
    f2h_kernel<<<(int)(3 * WE / 4 + 255) / 256, 256>>>(w_in, hwi, (int)(3 * WE / 4));
    f2h_kernel<<<(int)(WE / 4 + 255) / 256, 256>>>(w_out, hwo, (int)(WE / 4));

    dim3 gblk(256);

    // QKV projections: one batched launch, grid.z = 3
    gemm_h_kernel<1><<<dim3(EMBED / 128, MROWS / 128, 3), gblk>>>(
        hx, hwi, b_in, q, k, v, EMBED, EMBED, (long)NE, (long)WE, (long)EMBED);

    // Fused attention
    attn_h_kernel<<<dim3(TLEN / 128, BSZ * NHEAD), gblk, ATTN_SMEM>>>(q, k, v, o, attn);

    // Output projection (half in, float out)
    gemm_h_kernel<0><<<dim3(EMBED / 128, MROWS / 128, 1), gblk>>>(
        o, hwo, b_out, out, out, out, EMBED, EMBED, 0, 0, 0);
}